// round 11
// baseline (speedup 1.0000x reference)
#include <cuda_runtime.h>
#include <cuda_fp16.h>
#include <cstdint>

#define NN   100000
#define F    128
#define SLAB 128
#define NSTRIPS (NN / 16)         // 6250
#define WS_PAD 132
#define WS_BYTES (128 * WS_PAD * 4)   // 67584

// ---- scratch (no cudaMalloc allowed) --------------------------------------
__device__ __half g_xh[(size_t)NN * F];     // fp16(X @ W^T)  (25.6 MB)
__device__ float  g_deg[NN];                // 1 + count(col)
__device__ float  g_dinv[NN];               // rsqrt(deg)
__device__ int    g_cur[NN];                // slab fill counts
__device__ int    g_slab[(size_t)NN * SLAB];// per-row neighbor slabs (51.2 MB)
__device__ int    g_is64;

// ---------------------------------------------------------------------------
__global__ void detect_kernel(const long long* __restrict__ ei) {
    if (blockIdx.x == 0 && threadIdx.x == 0) {
        int is64 = 1;
        #pragma unroll 1
        for (int i = 0; i < 64; i++) {
            long long v = ei[i];
            if (v < 0 || v >= (long long)NN) { is64 = 0; break; }
        }
        g_is64 = is64;
    }
}

__device__ __forceinline__ int load_idx(const void* ei, long long i, int is64) {
    if (is64) return (int)((const long long*)ei)[i];
    return ((const int*)ei)[i];
}

__global__ void init_kernel() {
    int i = blockIdx.x * blockDim.x + threadIdx.x;
    if (i < NN) { g_deg[i] = 1.0f; g_cur[i] = 0; }
}

// ---------------------------------------------------------------------------
// Fused histogram + slab fill (1 edge/thread).
// ---------------------------------------------------------------------------
__global__ void edge_kernel(const void* __restrict__ ei, int E) {
    int e = blockIdx.x * blockDim.x + threadIdx.x;
    if (e >= E) return;
    int is64 = g_is64;
    int r = load_idx(ei, e, is64);
    int c = load_idx(ei, (long long)E + e, is64);
    atomicAdd(&g_deg[c], 1.0f);
    int pos = atomicAdd(&g_cur[r], 1);
    if (pos < SLAB) g_slab[(size_t)r * SLAB + pos] = c;
}

__global__ void dinv_kernel() {
    int i = blockIdx.x * blockDim.x + threadIdx.x;
    if (i < NN) g_dinv[i] = rsqrtf(g_deg[i]);
}

// ---------------------------------------------------------------------------
// TF32 tensor-core GEMM -> fp16 output: g_xh[i] = half(X[i] @ W^T)
// v2: column-split. Each warp: 16 rows x 64 cols (8 MMAs/k-step).
// 8 warps/block = 4 row-strips x 2 column halves. Higher occupancy.
// ---------------------------------------------------------------------------
__device__ __forceinline__ unsigned int f2tf32(float x) {
    unsigned int r;
    asm("cvt.rna.tf32.f32 %0, %1;" : "=r"(r) : "f"(x));
    return r;
}

__global__ void __launch_bounds__(256)
gemm_tf32_kernel(const float* __restrict__ X, const float* __restrict__ W) {
    extern __shared__ float Ws[];   // [128][WS_PAD], tf32-rounded W

    int t = threadIdx.x;
    #pragma unroll
    for (int i = 0; i < 16; i++) {
        int idx = t + i * 256;
        int n   = idx >> 5;
        int kq  = idx & 31;
        float4 v = *(const float4*)&W[(size_t)n * F + kq * 4];
        unsigned int* dst = (unsigned int*)&Ws[n * WS_PAD + kq * 4];
        dst[0] = f2tf32(v.x);
        dst[1] = f2tf32(v.y);
        dst[2] = f2tf32(v.z);
        dst[3] = f2tf32(v.w);
    }
    __syncthreads();

    int warp  = t >> 5;
    int lane  = t & 31;
    int strip = blockIdx.x * 4 + (warp >> 1);
    if (strip >= NSTRIPS) return;
    int ntbase = (warp & 1) * 8;     // column half: nt 0..7 or 8..15
    int brow = strip * 16;
    int gid = lane >> 2;   // 0..7
    int tig = lane & 3;    // 0..3

    float d[8][4];
    #pragma unroll
    for (int nt = 0; nt < 8; nt++)
        #pragma unroll
        for (int j = 0; j < 4; j++) d[nt][j] = 0.0f;

    const float* Xr0 = X + (size_t)(brow + gid) * F;
    const float* Xr1 = X + (size_t)(brow + gid + 8) * F;

    #pragma unroll 4
    for (int k0 = 0; k0 < F; k0 += 8) {
        unsigned int a0 = f2tf32(__ldg(&Xr0[k0 + tig]));
        unsigned int a1 = f2tf32(__ldg(&Xr1[k0 + tig]));
        unsigned int a2 = f2tf32(__ldg(&Xr0[k0 + tig + 4]));
        unsigned int a3 = f2tf32(__ldg(&Xr1[k0 + tig + 4]));

        #pragma unroll
        for (int nt = 0; nt < 8; nt++) {
            const unsigned int* wp = (const unsigned int*)
                &Ws[((ntbase + nt) * 8 + gid) * WS_PAD + k0 + tig];
            unsigned int b0 = wp[0];
            unsigned int b1 = wp[4];
            asm volatile(
                "mma.sync.aligned.m16n8k8.row.col.f32.tf32.tf32.f32 "
                "{%0,%1,%2,%3}, {%4,%5,%6,%7}, {%8,%9}, {%0,%1,%2,%3};"
                : "+f"(d[nt][0]), "+f"(d[nt][1]), "+f"(d[nt][2]), "+f"(d[nt][3])
                : "r"(a0), "r"(a1), "r"(a2), "r"(a3), "r"(b0), "r"(b1));
        }
    }

    int r0 = brow + gid;
    int r1 = brow + gid + 8;
    #pragma unroll
    for (int nt = 0; nt < 8; nt++) {
        int col = (ntbase + nt) * 8 + tig * 2;
        __half2 lo = __floats2half2_rn(d[nt][0], d[nt][1]);
        __half2 hi = __floats2half2_rn(d[nt][2], d[nt][3]);
        *(__half2*)&g_xh[(size_t)r0 * F + col] = lo;
        *(__half2*)&g_xh[(size_t)r1 * F + col] = hi;
    }
}

// ---------------------------------------------------------------------------
// Gather (R9 version): 2 rows per warp, 16 lanes per row, uint4 per lane.
// Warp-uniform loop bounds (reduce_max) with se=0 masking keep shfl legal.
// ---------------------------------------------------------------------------
__device__ __forceinline__ void acc8(float* acc, uint4 u, float s) {
    float2 f0 = __half22float2(*(__half2*)&u.x);
    float2 f1 = __half22float2(*(__half2*)&u.y);
    float2 f2 = __half22float2(*(__half2*)&u.z);
    float2 f3 = __half22float2(*(__half2*)&u.w);
    acc[0] += s * f0.x; acc[1] += s * f0.y;
    acc[2] += s * f1.x; acc[3] += s * f1.y;
    acc[4] += s * f2.x; acc[5] += s * f2.y;
    acc[6] += s * f3.x; acc[7] += s * f3.y;
}

__global__ void __launch_bounds__(256)
gather_kernel(float* __restrict__ out) {
    int gw   = (blockIdx.x * blockDim.x + threadIdx.x) >> 5;  // warp id
    int lane = threadIdx.x & 31;
    int half = lane >> 4;          // 0 or 1
    int l    = lane & 15;          // lane within half
    int r    = gw * 2 + half;      // NN even -> whole warp valid or invalid
    if (r >= NN) return;

    const uint4* xh4 = (const uint4*)g_xh;    // row = 16 uint4
    int   ne = min(g_cur[r], SLAB);
    float sr = g_dinv[r];
    int   ne_w = __reduce_max_sync(0xffffffffu, ne);  // warp-uniform bound

    float acc[8] = {0.f, 0.f, 0.f, 0.f, 0.f, 0.f, 0.f, 0.f};
    acc8(acc, xh4[(size_t)r * 16 + l], sr);   // self loop

    const int* slab = &g_slab[(size_t)r * SLAB];
    for (int base = 0; base < ne_w; base += 16) {
        // each half loads its 16-edge chunk; invalid lanes get se=0, ce=0
        int   ce = 0;
        float se = 0.0f;
        int   li = base + l;
        if (li < ne) {
            ce = slab[li];
            se = __ldg(&g_dinv[ce]);
        }
        int nw = min(16, ne_w - base);
        #pragma unroll 1
        for (int j = 0; j < nw; j += 4) {
            int src = half * 16 + j;
            int   c0 = __shfl_sync(0xffffffffu, ce, src + 0);
            int   c1 = __shfl_sync(0xffffffffu, ce, src + 1);
            int   c2 = __shfl_sync(0xffffffffu, ce, src + 2);
            int   c3 = __shfl_sync(0xffffffffu, ce, src + 3);
            float s0 = __shfl_sync(0xffffffffu, se, src + 0);
            float s1 = __shfl_sync(0xffffffffu, se, src + 1);
            float s2 = __shfl_sync(0xffffffffu, se, src + 2);
            float s3 = __shfl_sync(0xffffffffu, se, src + 3);
            uint4 u0 = xh4[(size_t)c0 * 16 + l];
            uint4 u1 = xh4[(size_t)c1 * 16 + l];
            uint4 u2 = xh4[(size_t)c2 * 16 + l];
            uint4 u3 = xh4[(size_t)c3 * 16 + l];
            acc8(acc, u0, s0);
            acc8(acc, u1, s1);
            acc8(acc, u2, s2);
            acc8(acc, u3, s3);
        }
    }

    float4 o0 = make_float4(acc[0] * sr, acc[1] * sr, acc[2] * sr, acc[3] * sr);
    float4 o1 = make_float4(acc[4] * sr, acc[5] * sr, acc[6] * sr, acc[7] * sr);
    float4* op = (float4*)out;
    __stcs(&op[(size_t)r * 32 + l * 2 + 0], o0);
    __stcs(&op[(size_t)r * 32 + l * 2 + 1], o1);
}

// ---------------------------------------------------------------------------
extern "C" void kernel_launch(void* const* d_in, const int* in_sizes, int n_in,
                              void* d_out, int out_size) {
    const float* X  = (const float*)d_in[0];
    const float* W  = (const float*)d_in[1];
    const void*  ei = d_in[2];
    int E = in_sizes[2] / 2;
    float* out = (float*)d_out;

    static cudaStream_t s2 = nullptr;
    static cudaEvent_t  evFork = nullptr, evJoin = nullptr;
    if (!s2) {
        cudaFuncSetAttribute(gemm_tf32_kernel,
                             cudaFuncAttributeMaxDynamicSharedMemorySize,
                             WS_BYTES);
        cudaStreamCreateWithFlags(&s2, cudaStreamNonBlocking);
        cudaEventCreateWithFlags(&evFork, cudaEventDisableTiming);
        cudaEventCreateWithFlags(&evJoin, cudaEventDisableTiming);
    }

    detect_kernel<<<1, 32>>>((const long long*)ei);
    init_kernel<<<(NN + 255) / 256, 256>>>();

    cudaEventRecord(evFork, 0);
    cudaStreamWaitEvent(s2, evFork, 0);
    gemm_tf32_kernel<<<(NSTRIPS + 3) / 4, 256, WS_BYTES, s2>>>(X, W);

    edge_kernel<<<(E + 255) / 256, 256>>>(ei, E);
    dinv_kernel<<<(NN + 255) / 256, 256>>>();

    cudaEventRecord(evJoin, s2);
    cudaStreamWaitEvent(0, evJoin, 0);
    gather_kernel<<<(NN / 2 * 32 + 255) / 256, 256>>>(out);
}

// round 12
// speedup vs baseline: 1.2383x; 1.2383x over previous
#include <cuda_runtime.h>
#include <cuda_fp16.h>
#include <cstdint>

#define NN   100000
#define F    128
#define SLAB 128
#define NSTRIPS (NN / 16)         // 6250
#define WS_PAD 132
#define WS_BYTES (128 * WS_PAD * 4)   // 67584

// ---- scratch (no cudaMalloc allowed) --------------------------------------
__device__ __half g_xh[(size_t)NN * F];     // fp16(X @ W^T)  (25.6 MB)
__device__ float  g_deg[NN];                // 1 + count(col)
__device__ float  g_dinv[NN];               // rsqrt(deg)
__device__ int    g_cur[NN];                // slab fill counts
__device__ int    g_slab[(size_t)NN * SLAB];// per-row neighbor slabs (51.2 MB)
__device__ int    g_is64;

// ---------------------------------------------------------------------------
__global__ void detect_kernel(const long long* __restrict__ ei) {
    if (blockIdx.x == 0 && threadIdx.x == 0) {
        int is64 = 1;
        #pragma unroll 1
        for (int i = 0; i < 64; i++) {
            long long v = ei[i];
            if (v < 0 || v >= (long long)NN) { is64 = 0; break; }
        }
        g_is64 = is64;
    }
}

__device__ __forceinline__ int load_idx(const void* ei, long long i, int is64) {
    if (is64) return (int)((const long long*)ei)[i];
    return ((const int*)ei)[i];
}

__global__ void init_kernel() {
    int i = blockIdx.x * blockDim.x + threadIdx.x;
    if (i < NN) { g_deg[i] = 1.0f; g_cur[i] = 0; }
}

// ---------------------------------------------------------------------------
// Fused histogram + slab fill (1 edge/thread).
// ---------------------------------------------------------------------------
__global__ void edge_kernel(const void* __restrict__ ei, int E) {
    int e = blockIdx.x * blockDim.x + threadIdx.x;
    if (e >= E) return;
    int is64 = g_is64;
    int r = load_idx(ei, e, is64);
    int c = load_idx(ei, (long long)E + e, is64);
    atomicAdd(&g_deg[c], 1.0f);
    int pos = atomicAdd(&g_cur[r], 1);
    if (pos < SLAB) g_slab[(size_t)r * SLAB + pos] = c;
}

__global__ void dinv_kernel() {
    int i = blockIdx.x * blockDim.x + threadIdx.x;
    if (i < NN) g_dinv[i] = rsqrtf(g_deg[i]);
}

// ---------------------------------------------------------------------------
// TF32 tensor-core GEMM -> fp16 output (R9 shape: 1 warp = 16 rows x 128 cols)
// ---------------------------------------------------------------------------
__device__ __forceinline__ unsigned int f2tf32(float x) {
    unsigned int r;
    asm("cvt.rna.tf32.f32 %0, %1;" : "=r"(r) : "f"(x));
    return r;
}

__global__ void __launch_bounds__(256)
gemm_tf32_kernel(const float* __restrict__ X, const float* __restrict__ W) {
    extern __shared__ float Ws[];   // [128][WS_PAD], tf32-rounded W

    int t = threadIdx.x;
    #pragma unroll
    for (int i = 0; i < 16; i++) {
        int idx = t + i * 256;
        int n   = idx >> 5;
        int kq  = idx & 31;
        float4 v = *(const float4*)&W[(size_t)n * F + kq * 4];
        unsigned int* dst = (unsigned int*)&Ws[n * WS_PAD + kq * 4];
        dst[0] = f2tf32(v.x);
        dst[1] = f2tf32(v.y);
        dst[2] = f2tf32(v.z);
        dst[3] = f2tf32(v.w);
    }
    __syncthreads();

    int warp  = t >> 5;
    int lane  = t & 31;
    int strip = blockIdx.x * 8 + warp;
    if (strip >= NSTRIPS) return;
    int brow = strip * 16;
    int gid = lane >> 2;   // 0..7
    int tig = lane & 3;    // 0..3

    float d[16][4];
    #pragma unroll
    for (int nt = 0; nt < 16; nt++)
        #pragma unroll
        for (int j = 0; j < 4; j++) d[nt][j] = 0.0f;

    const float* Xr0 = X + (size_t)(brow + gid) * F;
    const float* Xr1 = X + (size_t)(brow + gid + 8) * F;

    #pragma unroll 4
    for (int k0 = 0; k0 < F; k0 += 8) {
        unsigned int a0 = f2tf32(__ldg(&Xr0[k0 + tig]));
        unsigned int a1 = f2tf32(__ldg(&Xr1[k0 + tig]));
        unsigned int a2 = f2tf32(__ldg(&Xr0[k0 + tig + 4]));
        unsigned int a3 = f2tf32(__ldg(&Xr1[k0 + tig + 4]));

        #pragma unroll
        for (int nt = 0; nt < 16; nt++) {
            const unsigned int* wp =
                (const unsigned int*)&Ws[(nt * 8 + gid) * WS_PAD + k0 + tig];
            unsigned int b0 = wp[0];
            unsigned int b1 = wp[4];
            asm volatile(
                "mma.sync.aligned.m16n8k8.row.col.f32.tf32.tf32.f32 "
                "{%0,%1,%2,%3}, {%4,%5,%6,%7}, {%8,%9}, {%0,%1,%2,%3};"
                : "+f"(d[nt][0]), "+f"(d[nt][1]), "+f"(d[nt][2]), "+f"(d[nt][3])
                : "r"(a0), "r"(a1), "r"(a2), "r"(a3), "r"(b0), "r"(b1));
        }
    }

    int r0 = brow + gid;
    int r1 = brow + gid + 8;
    #pragma unroll
    for (int nt = 0; nt < 16; nt++) {
        __half2 lo = __floats2half2_rn(d[nt][0], d[nt][1]);
        __half2 hi = __floats2half2_rn(d[nt][2], d[nt][3]);
        *(__half2*)&g_xh[(size_t)r0 * F + nt * 8 + tig * 2] = lo;
        *(__half2*)&g_xh[(size_t)r1 * F + nt * 8 + tig * 2] = hi;
    }
}

// ---------------------------------------------------------------------------
// Gather (R9 + chunk prefetch): 2 rows/warp, 16 lanes/row, uint4 per lane.
// The slab+dinv loads for chunk i+1 are issued before processing chunk i,
// overlapping the next prologue's latency with this chunk's row loads.
// ---------------------------------------------------------------------------
__device__ __forceinline__ void acc8(float* acc, uint4 u, float s) {
    float2 f0 = __half22float2(*(__half2*)&u.x);
    float2 f1 = __half22float2(*(__half2*)&u.y);
    float2 f2 = __half22float2(*(__half2*)&u.z);
    float2 f3 = __half22float2(*(__half2*)&u.w);
    acc[0] += s * f0.x; acc[1] += s * f0.y;
    acc[2] += s * f1.x; acc[3] += s * f1.y;
    acc[4] += s * f2.x; acc[5] += s * f2.y;
    acc[6] += s * f3.x; acc[7] += s * f3.y;
}

__global__ void __launch_bounds__(256)
gather_kernel(float* __restrict__ out) {
    int gw   = (blockIdx.x * blockDim.x + threadIdx.x) >> 5;  // warp id
    int lane = threadIdx.x & 31;
    int half = lane >> 4;          // 0 or 1
    int l    = lane & 15;          // lane within half
    int r    = gw * 2 + half;      // NN even -> whole warp valid or invalid
    if (r >= NN) return;

    const uint4* xh4 = (const uint4*)g_xh;    // row = 16 uint4
    int   ne = min(g_cur[r], SLAB);
    float sr = g_dinv[r];
    int   ne_w = __reduce_max_sync(0xffffffffu, ne);  // warp-uniform bound

    float acc[8] = {0.f, 0.f, 0.f, 0.f, 0.f, 0.f, 0.f, 0.f};
    acc8(acc, xh4[(size_t)r * 16 + l], sr);   // self loop

    const int* slab = &g_slab[(size_t)r * SLAB];

    // Prologue for chunk 0.
    int   ce = 0;
    float se = 0.0f;
    if (l < ne) {
        ce = slab[l];
        se = __ldg(&g_dinv[ce]);
    }

    for (int base = 0; base < ne_w; base += 16) {
        // Prefetch chunk (base+16) before chewing on this one.
        int   ce_n = 0;
        float se_n = 0.0f;
        int   li = base + 16 + l;
        if (li < ne) {
            ce_n = slab[li];
            se_n = __ldg(&g_dinv[ce_n]);
        }

        int nw = min(16, ne_w - base);
        #pragma unroll 1
        for (int j = 0; j < nw; j += 4) {
            int src = half * 16 + j;
            int   c0 = __shfl_sync(0xffffffffu, ce, src + 0);
            int   c1 = __shfl_sync(0xffffffffu, ce, src + 1);
            int   c2 = __shfl_sync(0xffffffffu, ce, src + 2);
            int   c3 = __shfl_sync(0xffffffffu, ce, src + 3);
            float s0 = __shfl_sync(0xffffffffu, se, src + 0);
            float s1 = __shfl_sync(0xffffffffu, se, src + 1);
            float s2 = __shfl_sync(0xffffffffu, se, src + 2);
            float s3 = __shfl_sync(0xffffffffu, se, src + 3);
            uint4 u0 = xh4[(size_t)c0 * 16 + l];
            uint4 u1 = xh4[(size_t)c1 * 16 + l];
            uint4 u2 = xh4[(size_t)c2 * 16 + l];
            uint4 u3 = xh4[(size_t)c3 * 16 + l];
            acc8(acc, u0, s0);
            acc8(acc, u1, s1);
            acc8(acc, u2, s2);
            acc8(acc, u3, s3);
        }

        ce = ce_n;
        se = se_n;
    }

    float4 o0 = make_float4(acc[0] * sr, acc[1] * sr, acc[2] * sr, acc[3] * sr);
    float4 o1 = make_float4(acc[4] * sr, acc[5] * sr, acc[6] * sr, acc[7] * sr);
    float4* op = (float4*)out;
    __stcs(&op[(size_t)r * 32 + l * 2 + 0], o0);
    __stcs(&op[(size_t)r * 32 + l * 2 + 1], o1);
}

// ---------------------------------------------------------------------------
extern "C" void kernel_launch(void* const* d_in, const int* in_sizes, int n_in,
                              void* d_out, int out_size) {
    const float* X  = (const float*)d_in[0];
    const float* W  = (const float*)d_in[1];
    const void*  ei = d_in[2];
    int E = in_sizes[2] / 2;
    float* out = (float*)d_out;

    static cudaStream_t s2 = nullptr;
    static cudaEvent_t  evFork = nullptr, evJoin = nullptr;
    if (!s2) {
        cudaFuncSetAttribute(gemm_tf32_kernel,
                             cudaFuncAttributeMaxDynamicSharedMemorySize,
                             WS_BYTES);
        cudaStreamCreateWithFlags(&s2, cudaStreamNonBlocking);
        cudaEventCreateWithFlags(&evFork, cudaEventDisableTiming);
        cudaEventCreateWithFlags(&evJoin, cudaEventDisableTiming);
    }

    detect_kernel<<<1, 32>>>((const long long*)ei);
    init_kernel<<<(NN + 255) / 256, 256>>>();

    cudaEventRecord(evFork, 0);
    cudaStreamWaitEvent(s2, evFork, 0);
    gemm_tf32_kernel<<<(NSTRIPS + 7) / 8, 256, WS_BYTES, s2>>>(X, W);

    edge_kernel<<<(E + 255) / 256, 256>>>(ei, E);
    dinv_kernel<<<(NN + 255) / 256, 256>>>();

    cudaEventRecord(evJoin, s2);
    cudaStreamWaitEvent(0, evJoin, 0);
    gather_kernel<<<(NN / 2 * 32 + 255) / 256, 256>>>(out);
}